// round 8
// baseline (speedup 1.0000x reference)
#include <cuda_runtime.h>
#include <cuda_fp16.h>
#include <math.h>
#include <stdint.h>

#define K_CODES 1024
#define D 64
#define WIN 8e-5f
#define BIGF 3.4e38f

// dynamic smem layout (bytes)
#define OFF_ZSQ  0          // float[128]
#define OFF_ESQ  512        // float[1024]
#define OFF_B0   8192       // chunk buf0: eh fp16, 128 codes x 128B = 16KB
#define OFF_B1   24576      // chunk buf1
#define OFF_WIDX 40960      // int[128]  (bit31 = needs exact rescan)
#define OFF_BSUM 41472      // float
#define SMEM_SZ  41600

__device__ unsigned int g_counts[K_CODES];
__device__ float g_esq[K_CODES];
__device__ double g_sumsq;
__device__ __align__(16) __half g_eh[K_CODES * D];   // codebook * 1024 in fp16

// ---------------- helpers ----------------
__device__ __forceinline__ uint32_t smem_u32(const void* p) {
    uint32_t a;
    asm("{ .reg .u64 t; cvta.to.shared.u64 t, %1; cvt.u32.u64 %0, t; }" : "=r"(a) : "l"(p));
    return a;
}
__device__ __forceinline__ void ldsm4(uint32_t* r, uint32_t addr) {
    asm volatile("ldmatrix.sync.aligned.m8n8.x4.shared.b16 {%0,%1,%2,%3}, [%4];"
                 : "=r"(r[0]), "=r"(r[1]), "=r"(r[2]), "=r"(r[3]) : "r"(addr));
}
__device__ __forceinline__ void mma16816(float* c, const uint32_t* a, uint32_t b0, uint32_t b1) {
    asm volatile(
        "mma.sync.aligned.m16n8k16.row.col.f32.f16.f16.f32 "
        "{%0,%1,%2,%3}, {%4,%5,%6,%7}, {%8,%9}, {%0,%1,%2,%3};"
        : "+f"(c[0]), "+f"(c[1]), "+f"(c[2]), "+f"(c[3])
        : "r"(a[0]), "r"(a[1]), "r"(a[2]), "r"(a[3]), "r"(b0), "r"(b1));
}
// exact score, R1's accumulation order (even/odd fmaf chains)
__device__ __forceinline__ float exact_score(const float* zr, const float* er,
                                             float zsq, float esq) {
    float aE = 0.f, aO = 0.f;
#pragma unroll
    for (int i = 0; i < 16; ++i) {
        float4 v = ((const float4*)zr)[i];
        float4 c = ((const float4*)er)[i];
        aE = fmaf(v.x, c.x, aE); aE = fmaf(v.z, c.z, aE);
        aO = fmaf(v.y, c.y, aO); aO = fmaf(v.w, c.w, aO);
    }
    return (zsq - 2.0f * (aE + aO)) + esq;
}
// track (b1,i1,b2); codes arrive in ascending idx => strict '<' keeps lowest idx
__device__ __forceinline__ void track(float& b1, int& i1, float& b2, float s, int idx) {
    if (s < b2) {
        if (s < b1) { b2 = b1; b1 = s; i1 = idx; }
        else b2 = s;
    }
}

// ---------------------------------------------------------------------------
// Kernel 0: zero scratch + esq + fp16 (x1024) codebook
// ---------------------------------------------------------------------------
__global__ void vq_prep(const float* __restrict__ cb) {
    int k = blockIdx.x * blockDim.x + threadIdx.x;
    if (k >= K_CODES) return;
    g_counts[k] = 0u;
    if (k == 0) g_sumsq = 0.0;
    const float4* cr = (const float4*)(cb + (size_t)k * D);
    uint2* oh = (uint2*)(g_eh + (size_t)k * D);
    float s = 0.f;
#pragma unroll
    for (int i = 0; i < 16; ++i) {
        float4 v = cr[i];
        s = fmaf(v.x, v.x, s); s = fmaf(v.y, v.y, s);
        s = fmaf(v.z, v.z, s); s = fmaf(v.w, v.w, s);
        __half2 h01 = __floats2half2_rn(v.x * 1024.f, v.y * 1024.f);
        __half2 h23 = __floats2half2_rn(v.z * 1024.f, v.w * 1024.f);
        oh[i] = make_uint2(*(uint32_t*)&h01, *(uint32_t*)&h23);
    }
    g_esq[k] = s;
}

// ---------------------------------------------------------------------------
// stage a 128-code chunk of eh into smem with 16B-block XOR swizzle (16KB)
// ---------------------------------------------------------------------------
__device__ __forceinline__ void stage_chunk(char* dst, int ch, int tid) {
    const uint4* sh = (const uint4*)((const char*)g_eh + (size_t)ch * 16384);
#pragma unroll
    for (int it = 0; it < 4; ++it) {
        int b = it * 256 + tid;
        int row = b >> 3, blk = b & 7;
        int off = row * 128 + ((blk ^ (row & 7)) << 4);
        *(uint4*)(dst + off) = sh[b];
    }
}

// ---------------------------------------------------------------------------
// Fused kernel: fp16 HMMA (software-pipelined) -> argmin + rescue -> epilogue
//   CTA: 128 tokens, 256 thr (8 warps x 16 tokens); codes in 8 chunks of 128.
//   launch_bounds (256,2): 128-reg budget -- (256,3) spills, do not tighten.
// ---------------------------------------------------------------------------
__global__ __launch_bounds__(256, 2) void vq_mma(const float* __restrict__ z,
                                                 const float* __restrict__ cb,
                                                 float* __restrict__ out, int N) {
    extern __shared__ __align__(1024) char smb[];
    const uint32_t sb = smem_u32(smb);
    float* zsq_s = (float*)(smb + OFF_ZSQ);
    float* esq_s = (float*)(smb + OFF_ESQ);
    int* widx_s = (int*)(smb + OFF_WIDX);
    float* bsum_s = (float*)(smb + OFF_BSUM);
    const int tid = threadIdx.x;
    const int w = tid >> 5, l = tid & 31;
    const int tok0 = blockIdx.x * 128;

    if (tid == 0) *bsum_s = 0.f;
    if (tid < 128) {   // zsq, sequential d ascending (matches R1)
        const float4* zr = (const float4*)(z + (size_t)(tok0 + tid) * D);
        float s = 0.f;
#pragma unroll
        for (int i = 0; i < 16; ++i) {
            float4 v = zr[i];
            s = fmaf(v.x, v.x, s); s = fmaf(v.y, v.y, s);
            s = fmaf(v.z, v.z, s); s = fmaf(v.w, v.w, s);
        }
        zsq_s[tid] = s;
    }
    for (int i = tid; i < K_CODES; i += 256) esq_s[i] = g_esq[i];

    // A fragments (fp16 z) straight from gmem
    const int r0 = w * 16 + (l >> 2), r1 = r0 + 8;
    uint32_t ah[4][4];
    {
        const float* zb = z + (size_t)tok0 * D;
#pragma unroll
        for (int ks = 0; ks < 4; ++ks) {
            int c = ks * 16 + (l & 3) * 2;
#pragma unroll
            for (int q = 0; q < 4; ++q) {
                int rr = (q & 1) ? r1 : r0;
                int cc = c + ((q >> 1) ? 8 : 0);
                float2 v = *(const float2*)(zb + (size_t)rr * D + cc);
                __half2 h = __floats2half2_rn(v.x, v.y);
                ah[ks][q] = *(uint32_t*)&h;
            }
        }
    }

    stage_chunk(smb + OFF_B0, 0, tid);
    __syncthreads();

    float b1a = BIGF, b2a = BIGF, b1b = BIGF, b2b = BIGF;
    int i1a = 0x7FFFFFFF, i1b = 0x7FFFFFFF;
    const float SC = -0.001953125f;   // -2 / 1024, exact
    const int lc2 = (l & 3) * 2;

    const int g = l >> 3, ii = l & 7;
    for (int ch = 0; ch < 8; ++ch) {
        const int cur = ch & 1;
        if (ch < 7) stage_chunk(smb + (cur ? OFF_B0 : OFF_B1), ch + 1, tid);
        uint32_t bb = sb + (cur ? OFF_B1 : OFF_B0);
        uint32_t baseLo = bb + ii * 128 + ((g ^ ii) << 4);
        uint32_t baseHi = bb + ii * 128 + (((g + 4) ^ ii) << 4);
        const int chbase = ch * 128 + lc2;

        // ---- software pipeline: issue j, track j-1 ----
        uint32_t eh[2][8];
        float acc[2][4];
        float2 eq[2];

        // prologue: j = 0
        ldsm4(eh[0], baseLo);
        ldsm4(eh[0] + 4, baseHi);
        acc[0][0] = acc[0][1] = acc[0][2] = acc[0][3] = 0.f;
#pragma unroll
        for (int ks = 0; ks < 4; ++ks)
            mma16816(acc[0], ah[ks], eh[0][2 * ks], eh[0][2 * ks + 1]);
        eq[0] = *(const float2*)(esq_s + chbase);

#pragma unroll
        for (int j = 1; j < 16; ++j) {
            const int c_ = j & 1, p_ = c_ ^ 1;
            ldsm4(eh[c_], baseLo + j * 1024);
            ldsm4(eh[c_] + 4, baseHi + j * 1024);
            acc[c_][0] = acc[c_][1] = acc[c_][2] = acc[c_][3] = 0.f;
#pragma unroll
            for (int ks = 0; ks < 4; ++ks)
                mma16816(acc[c_], ah[ks], eh[c_][2 * ks], eh[c_][2 * ks + 1]);
            eq[c_] = *(const float2*)(esq_s + chbase + j * 8);

            // track previous j
            int code0 = chbase + (j - 1) * 8;
            track(b1a, i1a, b2a, fmaf(acc[p_][0], SC, eq[p_].x), code0);
            track(b1a, i1a, b2a, fmaf(acc[p_][1], SC, eq[p_].y), code0 + 1);
            track(b1b, i1b, b2b, fmaf(acc[p_][2], SC, eq[p_].x), code0);
            track(b1b, i1b, b2b, fmaf(acc[p_][3], SC, eq[p_].y), code0 + 1);
        }
        // drain: j = 15 (parity 1)
        {
            int code0 = chbase + 15 * 8;
            track(b1a, i1a, b2a, fmaf(acc[1][0], SC, eq[1].x), code0);
            track(b1a, i1a, b2a, fmaf(acc[1][1], SC, eq[1].y), code0 + 1);
            track(b1b, i1b, b2b, fmaf(acc[1][2], SC, eq[1].x), code0);
            track(b1b, i1b, b2b, fmaf(acc[1][3], SC, eq[1].y), code0 + 1);
        }
        __syncthreads();
    }

    // quad reduce (lanes 4g..4g+3 hold rows r0, r1)
#pragma unroll
    for (int o = 1; o <= 2; o <<= 1) {
        float ob1 = __shfl_xor_sync(~0u, b1a, o);
        int oi1 = __shfl_xor_sync(~0u, i1a, o);
        float ob2 = __shfl_xor_sync(~0u, b2a, o);
        b2a = fminf(fminf(b2a, ob2), fmaxf(b1a, ob1));
        if (ob1 < b1a || (ob1 == b1a && oi1 < i1a)) { b1a = ob1; i1a = oi1; }
        ob1 = __shfl_xor_sync(~0u, b1b, o);
        oi1 = __shfl_xor_sync(~0u, i1b, o);
        ob2 = __shfl_xor_sync(~0u, b2b, o);
        b2b = fminf(fminf(b2b, ob2), fmaxf(b1b, ob1));
        if (ob1 < b1b || (ob1 == b1b && oi1 < i1b)) { b1b = ob1; i1b = oi1; }
    }
    if ((l & 3) == 0) {
        widx_s[r0] = i1a | ((b2a < b1a + WIN) ? 0x80000000 : 0);
        widx_s[r1] = i1b | ((b2b < b1b + WIN) ? 0x80000000 : 0);
    }
    __syncwarp();

    // exact rescue for ambiguous tokens (warp-cooperative, ascending code order)
    for (int t = 0; t < 16; ++t) {
        int lt = w * 16 + t;
        if (widx_s[lt] < 0) {
            const float* zr = z + (size_t)(tok0 + lt) * D;
            float zsq = zsq_s[lt];
            float s = BIGF;
            int bi = 0x7FFFFFFF;
            for (int c = l * 32; c < l * 32 + 32; ++c) {
                float sc = exact_score(zr, cb + (size_t)c * D, zsq, esq_s[c]);
                if (sc < s) { s = sc; bi = c; }
            }
#pragma unroll
            for (int o = 16; o > 0; o >>= 1) {
                float s2 = __shfl_xor_sync(~0u, s, o);
                int i2 = __shfl_xor_sync(~0u, bi, o);
                if (s2 < s || (s2 == s && i2 < bi)) { s = s2; bi = i2; }
            }
            if (l == 0) widx_s[lt] = bi;
        }
    }
    __syncthreads();

    // ---- epilogue: indices, histogram, z_q straight-through, sumsq ----
    if (tid < 128) {
        int bi = widx_s[tid] & 0x7FFFFFFF;
        out[(size_t)N * D + tok0 + tid] = (float)bi;
        atomicAdd(&g_counts[bi], 1u);
    }
    {
        int t = tid >> 1, half = tid & 1;
        int bi = widx_s[t] & 0x7FFFFFFF;
        const float4* cr = (const float4*)(cb + (size_t)bi * D + half * 32);
        const float4* zr = (const float4*)(z + (size_t)(tok0 + t) * D + half * 32);
        float4* orow = (float4*)(out + (size_t)(tok0 + t) * D + half * 32);
        float part = 0.f;
#pragma unroll
        for (int i = 0; i < 8; ++i) {
            float4 cv = cr[i], zv = zr[i];
            float dx = cv.x - zv.x, dy = cv.y - zv.y;
            float dz = cv.z - zv.z, dw = cv.w - zv.w;
            orow[i] = make_float4(zv.x + dx, zv.y + dy, zv.z + dz, zv.w + dw);
            part += dx * dx + dy * dy + dz * dz + dw * dw;
        }
#pragma unroll
        for (int o = 16; o > 0; o >>= 1) part += __shfl_xor_sync(~0u, part, o);
        if (l == 0) atomicAdd(bsum_s, part);
    }
    __syncthreads();
    if (tid == 0) atomicAdd(&g_sumsq, (double)*bsum_s);
}

// ---------------------------------------------------------------------------
// Finalize: entropy / perplexity / losses (fp32, like the reference)
// ---------------------------------------------------------------------------
__global__ void vq_finalize(float* __restrict__ out, int N) {
    int k = threadIdx.x, lane = k & 31, w = k >> 5;
    float avg = (float)g_counts[k] / (float)N + 1e-10f;
    float term = -avg * logf(avg);
#pragma unroll
    for (int o = 16; o > 0; o >>= 1) term += __shfl_xor_sync(~0u, term, o);
    __shared__ float ws[32];
    if (lane == 0) ws[w] = term;
    __syncthreads();
    if (w == 0) {
        float v = ws[lane];
#pragma unroll
        for (int o = 16; o > 0; o >>= 1) v += __shfl_xor_sync(~0u, v, o);
        if (lane == 0) {
            float H = v;
            double mean = g_sumsq / ((double)N * D);
            size_t base = (size_t)N * D + N;
            out[base + 0] = (float)mean;
            out[base + 1] = (float)(0.25 * mean);
            out[base + 2] = -0.1f * (H / logf(1024.0f));
            out[base + 3] = expf(H);
        }
    }
}

// ---------------------------------------------------------------------------
extern "C" void kernel_launch(void* const* d_in, const int* in_sizes, int n_in,
                              void* d_out, int out_size) {
    const float* z = (const float*)d_in[0];
    const float* cb = (const float*)d_in[1];
    float* out = (float*)d_out;
    int N = in_sizes[0] / D;

    cudaFuncSetAttribute(vq_mma, cudaFuncAttributeMaxDynamicSharedMemorySize, SMEM_SZ);

    vq_prep<<<8, 128>>>(cb);
    vq_mma<<<N / 128, 256, SMEM_SZ>>>(z, cb, out, N);
    vq_finalize<<<1, 1024>>>(out, N);
}

// round 9
// speedup vs baseline: 1.2603x; 1.2603x over previous
#include <cuda_runtime.h>
#include <cuda_bf16.h>
#include <math.h>
#include <stdint.h>

#define K_CODES 1024
#define D 64
#define WIN 3e-5f
#define BIGF 3.4e38f

// dynamic smem layout (bytes)
#define OFF_ZSQ  0          // float[128]
#define OFF_ESQ  512        // float[1024]
#define OFF_B0   8192       // chunk buf0: eh 16KB + el 16KB
#define OFF_B1   40960      // chunk buf1
#define OFF_WIDX 73728      // int[128]  (bit31 = needs exact rescan)
#define OFF_BSUM 74240      // float
#define SMEM_SZ  74304

__device__ unsigned int g_counts[K_CODES];
__device__ float g_esq[K_CODES];
__device__ double g_sumsq;
__device__ __align__(16) __nv_bfloat16 g_eh[K_CODES * D];
__device__ __align__(16) __nv_bfloat16 g_el[K_CODES * D];

// ---------------- helpers ----------------
__device__ __forceinline__ uint32_t smem_u32(const void* p) {
    uint32_t a;
    asm("{ .reg .u64 t; cvta.to.shared.u64 t, %1; cvt.u32.u64 %0, t; }" : "=r"(a) : "l"(p));
    return a;
}
__device__ __forceinline__ void ldsm4(uint32_t* r, uint32_t addr) {
    asm volatile("ldmatrix.sync.aligned.m8n8.x4.shared.b16 {%0,%1,%2,%3}, [%4];"
                 : "=r"(r[0]), "=r"(r[1]), "=r"(r[2]), "=r"(r[3]) : "r"(addr));
}
__device__ __forceinline__ void mma16816(float* c, const uint32_t* a, uint32_t b0, uint32_t b1) {
    asm volatile(
        "mma.sync.aligned.m16n8k16.row.col.f32.bf16.bf16.f32 "
        "{%0,%1,%2,%3}, {%4,%5,%6,%7}, {%8,%9}, {%0,%1,%2,%3};"
        : "+f"(c[0]), "+f"(c[1]), "+f"(c[2]), "+f"(c[3])
        : "r"(a[0]), "r"(a[1]), "r"(a[2]), "r"(a[3]), "r"(b0), "r"(b1));
}
// exact score, R1's accumulation order (even/odd fmaf chains)
__device__ __forceinline__ float exact_score(const float* zr, const float* er,
                                             float zsq, float esq) {
    float aE = 0.f, aO = 0.f;
#pragma unroll
    for (int i = 0; i < 16; ++i) {
        float4 v = ((const float4*)zr)[i];
        float4 c = ((const float4*)er)[i];
        aE = fmaf(v.x, c.x, aE); aE = fmaf(v.z, c.z, aE);
        aO = fmaf(v.y, c.y, aO); aO = fmaf(v.w, c.w, aO);
    }
    return (zsq - 2.0f * (aE + aO)) + esq;
}
// track (b1,i1,b2); codes arrive in ascending idx => strict '<' keeps lowest idx
__device__ __forceinline__ void track(float& b1, int& i1, float& b2, float s, int idx) {
    if (s < b2) {
        if (s < b1) { b2 = b1; b1 = s; i1 = idx; }
        else b2 = s;
    }
}

// ---------------------------------------------------------------------------
// Kernel 0: zero scratch + esq + bf16 splits of codebook
// ---------------------------------------------------------------------------
__global__ void vq_prep(const float* __restrict__ cb) {
    int k = blockIdx.x * blockDim.x + threadIdx.x;
    if (k >= K_CODES) return;
    g_counts[k] = 0u;
    if (k == 0) g_sumsq = 0.0;
    const float4* cr = (const float4*)(cb + (size_t)k * D);
    uint2* oh = (uint2*)(g_eh + (size_t)k * D);
    uint2* ol = (uint2*)(g_el + (size_t)k * D);
    float s = 0.f;
#pragma unroll
    for (int i = 0; i < 16; ++i) {
        float4 v = cr[i];
        s = fmaf(v.x, v.x, s); s = fmaf(v.y, v.y, s);
        s = fmaf(v.z, v.z, s); s = fmaf(v.w, v.w, s);
        __nv_bfloat162 h01, h23, l01, l23;
        h01.x = __float2bfloat16(v.x); h01.y = __float2bfloat16(v.y);
        h23.x = __float2bfloat16(v.z); h23.y = __float2bfloat16(v.w);
        l01.x = __float2bfloat16(v.x - __bfloat162float(h01.x));
        l01.y = __float2bfloat16(v.y - __bfloat162float(h01.y));
        l23.x = __float2bfloat16(v.z - __bfloat162float(h23.x));
        l23.y = __float2bfloat16(v.w - __bfloat162float(h23.y));
        oh[i] = make_uint2(*(uint32_t*)&h01, *(uint32_t*)&h23);
        ol[i] = make_uint2(*(uint32_t*)&l01, *(uint32_t*)&l23);
    }
    g_esq[k] = s;
}

// ---------------------------------------------------------------------------
// stage a 128-code chunk of (eh, el) into smem with 16B-block XOR swizzle
// ---------------------------------------------------------------------------
__device__ __forceinline__ void stage_chunk(char* dst, int ch, int tid) {
    const uint4* sh = (const uint4*)((const char*)g_eh + (size_t)ch * 16384);
    const uint4* sl = (const uint4*)((const char*)g_el + (size_t)ch * 16384);
#pragma unroll
    for (int it = 0; it < 4; ++it) {
        int b = it * 256 + tid;
        int row = b >> 3, blk = b & 7;
        int off = row * 128 + ((blk ^ (row & 7)) << 4);
        *(uint4*)(dst + off) = sh[b];
        *(uint4*)(dst + 16384 + off) = sl[b];
    }
}

// ---------------------------------------------------------------------------
// Fused kernel: HMMA scan (screened argmin) + exact rescue + full epilogue
//   CTA: 128 tokens, 256 thr (8 warps x 16 tokens); codes in 8 chunks of 128.
// ---------------------------------------------------------------------------
__global__ __launch_bounds__(256, 2) void vq_mma(const float* __restrict__ z,
                                                 const float* __restrict__ cb,
                                                 float* __restrict__ out, int N) {
    extern __shared__ __align__(1024) char smb[];
    const uint32_t sb = smem_u32(smb);
    float* zsq_s = (float*)(smb + OFF_ZSQ);
    float* esq_s = (float*)(smb + OFF_ESQ);
    int* widx_s = (int*)(smb + OFF_WIDX);
    float* bsum_s = (float*)(smb + OFF_BSUM);
    const int tid = threadIdx.x;
    const int w = tid >> 5, l = tid & 31;
    const int tok0 = blockIdx.x * 128;

    if (tid == 0) *bsum_s = 0.f;
    if (tid < 128) {   // zsq, sequential d ascending (matches R1)
        const float4* zr = (const float4*)(z + (size_t)(tok0 + tid) * D);
        float s = 0.f;
#pragma unroll
        for (int i = 0; i < 16; ++i) {
            float4 v = zr[i];
            s = fmaf(v.x, v.x, s); s = fmaf(v.y, v.y, s);
            s = fmaf(v.z, v.z, s); s = fmaf(v.w, v.w, s);
        }
        zsq_s[tid] = s;
    }
    for (int i = tid; i < K_CODES; i += 256) esq_s[i] = g_esq[i];

    // A fragments (zh, zl) straight from gmem
    const int r0 = w * 16 + (l >> 2), r1 = r0 + 8;
    uint32_t ah[4][4], al[4][4];
    {
        const float* zb = z + (size_t)tok0 * D;
#pragma unroll
        for (int ks = 0; ks < 4; ++ks) {
            int c = ks * 16 + (l & 3) * 2;
#pragma unroll
            for (int q = 0; q < 4; ++q) {
                int rr = (q & 1) ? r1 : r0;
                int cc = c + ((q >> 1) ? 8 : 0);
                float2 v = *(const float2*)(zb + (size_t)rr * D + cc);
                __nv_bfloat162 h, lo;
                h.x = __float2bfloat16(v.x); h.y = __float2bfloat16(v.y);
                lo.x = __float2bfloat16(v.x - __bfloat162float(h.x));
                lo.y = __float2bfloat16(v.y - __bfloat162float(h.y));
                ah[ks][q] = *(uint32_t*)&h;
                al[ks][q] = *(uint32_t*)&lo;
            }
        }
    }

    stage_chunk(smb + OFF_B0, 0, tid);
    __syncthreads();
    const float zs0 = zsq_s[w * 16 + (l >> 2)];
    const float zs1 = zsq_s[w * 16 + (l >> 2) + 8];

    float b1a = BIGF, b2a = BIGF, b1b = BIGF, b2b = BIGF;
    int i1a = 0x7FFFFFFF, i1b = 0x7FFFFFFF;

    const int g = l >> 3, ii = l & 7;
    for (int ch = 0; ch < 8; ++ch) {
        const int cur = ch & 1;
        if (ch < 7) stage_chunk(smb + (cur ? OFF_B0 : OFF_B1), ch + 1, tid);
        uint32_t bb = sb + (cur ? OFF_B1 : OFF_B0);
        uint32_t baseLo = bb + ii * 128 + ((g ^ ii) << 4);
        uint32_t baseHi = bb + ii * 128 + (((g + 4) ^ ii) << 4);
#pragma unroll 4
        for (int j = 0; j < 16; ++j) {
            uint32_t eh[8], el[8];
            ldsm4(eh, baseLo + j * 1024);
            ldsm4(eh + 4, baseHi + j * 1024);
            ldsm4(el, baseLo + 16384 + j * 1024);
            ldsm4(el + 4, baseHi + 16384 + j * 1024);
            float acc[4] = {0.f, 0.f, 0.f, 0.f};
#pragma unroll
            for (int ks = 0; ks < 4; ++ks) mma16816(acc, ah[ks], eh[2 * ks], eh[2 * ks + 1]);
#pragma unroll
            for (int ks = 0; ks < 4; ++ks) mma16816(acc, al[ks], eh[2 * ks], eh[2 * ks + 1]);
#pragma unroll
            for (int ks = 0; ks < 4; ++ks) mma16816(acc, ah[ks], el[2 * ks], el[2 * ks + 1]);

            int code0 = ch * 128 + j * 8 + (l & 3) * 2;
            float2 eq = *(const float2*)(esq_s + code0);
            float s00 = (zs0 - 2.f * acc[0]) + eq.x;
            float s01 = (zs0 - 2.f * acc[1]) + eq.y;
            float s10 = (zs1 - 2.f * acc[2]) + eq.x;
            float s11 = (zs1 - 2.f * acc[3]) + eq.y;
            // screened update: any score that can change (b1,i1,b2) has s < b2,
            // so the fminf screen is exact; inside, original ascending tracks.
            if (fminf(s00, s01) < b2a) {
                track(b1a, i1a, b2a, s00, code0);
                track(b1a, i1a, b2a, s01, code0 + 1);
            }
            if (fminf(s10, s11) < b2b) {
                track(b1b, i1b, b2b, s10, code0);
                track(b1b, i1b, b2b, s11, code0 + 1);
            }
        }
        __syncthreads();
    }

    // quad reduce (lanes 4g..4g+3 hold rows r0, r1)
#pragma unroll
    for (int o = 1; o <= 2; o <<= 1) {
        float ob1 = __shfl_xor_sync(~0u, b1a, o);
        int oi1 = __shfl_xor_sync(~0u, i1a, o);
        float ob2 = __shfl_xor_sync(~0u, b2a, o);
        b2a = fminf(fminf(b2a, ob2), fmaxf(b1a, ob1));
        if (ob1 < b1a || (ob1 == b1a && oi1 < i1a)) { b1a = ob1; i1a = oi1; }
        ob1 = __shfl_xor_sync(~0u, b1b, o);
        oi1 = __shfl_xor_sync(~0u, i1b, o);
        ob2 = __shfl_xor_sync(~0u, b2b, o);
        b2b = fminf(fminf(b2b, ob2), fmaxf(b1b, ob1));
        if (ob1 < b1b || (ob1 == b1b && oi1 < i1b)) { b1b = ob1; i1b = oi1; }
    }
    if ((l & 3) == 0) {
        widx_s[r0] = i1a | ((b2a < b1a + WIN) ? 0x80000000 : 0);
        widx_s[r1] = i1b | ((b2b < b1b + WIN) ? 0x80000000 : 0);
    }
    __syncwarp();

    // exact rescue for ambiguous tokens (warp-cooperative, ascending code order)
    for (int t = 0; t < 16; ++t) {
        int lt = w * 16 + t;
        if (widx_s[lt] < 0) {
            const float* zr = z + (size_t)(tok0 + lt) * D;
            float zsq = zsq_s[lt];
            float s = BIGF;
            int bi = 0x7FFFFFFF;
            for (int c = l * 32; c < l * 32 + 32; ++c) {
                float sc = exact_score(zr, cb + (size_t)c * D, zsq, esq_s[c]);
                if (sc < s) { s = sc; bi = c; }
            }
#pragma unroll
            for (int o = 16; o > 0; o >>= 1) {
                float s2 = __shfl_xor_sync(~0u, s, o);
                int i2 = __shfl_xor_sync(~0u, bi, o);
                if (s2 < s || (s2 == s && i2 < bi)) { s = s2; bi = i2; }
            }
            if (l == 0) widx_s[lt] = bi;
        }
    }
    __syncthreads();

    // ---- epilogue: indices, histogram, z_q straight-through, sumsq ----
    if (tid < 128) {
        int bi = widx_s[tid] & 0x7FFFFFFF;
        out[(size_t)N * D + tok0 + tid] = (float)bi;
        atomicAdd(&g_counts[bi], 1u);
    }
    {
        int t = tid >> 1, half = tid & 1;
        int bi = widx_s[t] & 0x7FFFFFFF;
        const float4* cr = (const float4*)(cb + (size_t)bi * D + half * 32);
        const float4* zr = (const float4*)(z + (size_t)(tok0 + t) * D + half * 32);
        float4* orow = (float4*)(out + (size_t)(tok0 + t) * D + half * 32);
        float part = 0.f;
#pragma unroll
        for (int i = 0; i < 8; ++i) {
            float4 cv = cr[i], zv = zr[i];
            float dx = cv.x - zv.x, dy = cv.y - zv.y;
            float dz = cv.z - zv.z, dw = cv.w - zv.w;
            orow[i] = make_float4(zv.x + dx, zv.y + dy, zv.z + dz, zv.w + dw);
            part += dx * dx + dy * dy + dz * dz + dw * dw;
        }
#pragma unroll
        for (int o = 16; o > 0; o >>= 1) part += __shfl_xor_sync(~0u, part, o);
        if (l == 0) atomicAdd(bsum_s, part);
    }
    __syncthreads();
    if (tid == 0) atomicAdd(&g_sumsq, (double)*bsum_s);
}

// ---------------------------------------------------------------------------
// Finalize: entropy / perplexity / losses (fp32, like the reference)
// ---------------------------------------------------------------------------
__global__ void vq_finalize(float* __restrict__ out, int N) {
    int k = threadIdx.x, lane = k & 31, w = k >> 5;
    float avg = (float)g_counts[k] / (float)N + 1e-10f;
    float term = -avg * logf(avg);
#pragma unroll
    for (int o = 16; o > 0; o >>= 1) term += __shfl_xor_sync(~0u, term, o);
    __shared__ float ws[32];
    if (lane == 0) ws[w] = term;
    __syncthreads();
    if (w == 0) {
        float v = ws[lane];
#pragma unroll
        for (int o = 16; o > 0; o >>= 1) v += __shfl_xor_sync(~0u, v, o);
        if (lane == 0) {
            float H = v;
            double mean = g_sumsq / ((double)N * D);
            size_t base = (size_t)N * D + N;
            out[base + 0] = (float)mean;
            out[base + 1] = (float)(0.25 * mean);
            out[base + 2] = -0.1f * (H / logf(1024.0f));
            out[base + 3] = expf(H);
        }
    }
}

// ---------------------------------------------------------------------------
extern "C" void kernel_launch(void* const* d_in, const int* in_sizes, int n_in,
                              void* d_out, int out_size) {
    const float* z = (const float*)d_in[0];
    const float* cb = (const float*)d_in[1];
    float* out = (float*)d_out;
    int N = in_sizes[0] / D;

    cudaFuncSetAttribute(vq_mma, cudaFuncAttributeMaxDynamicSharedMemorySize, SMEM_SZ);

    vq_prep<<<8, 128>>>(cb);
    vq_mma<<<N / 128, 256, SMEM_SZ>>>(z, cb, out, N);
    vq_finalize<<<1, 1024>>>(out, N);
}

// round 10
// speedup vs baseline: 1.5310x; 1.2148x over previous
#include <cuda_runtime.h>
#include <cuda_fp16.h>
#include <math.h>
#include <stdint.h>

#define K_CODES 1024
#define D 64
#define WIN 3e-5f
#define BIGF 3.4e38f

// dynamic smem layout (bytes)
#define OFF_ZSQ  0          // float[128]
#define OFF_ESQ  512        // float[1024]
#define OFF_B0   8192       // chunk buf0: e16 (x1024), 128 codes x 128B = 16KB
#define OFF_B1   24576      // chunk buf1
#define OFF_WIDX 40960      // int[128]  (bit31 = needs exact rescan)
#define OFF_BSUM 41472      // float
#define SMEM_SZ  41600

__device__ unsigned int g_counts[K_CODES];
__device__ float g_esq[K_CODES];
__device__ double g_sumsq;
__device__ __align__(16) __half g_e16[K_CODES * D];   // codebook * 1024, fp16

// ---------------- helpers ----------------
__device__ __forceinline__ uint32_t smem_u32(const void* p) {
    uint32_t a;
    asm("{ .reg .u64 t; cvta.to.shared.u64 t, %1; cvt.u32.u64 %0, t; }" : "=r"(a) : "l"(p));
    return a;
}
__device__ __forceinline__ void ldsm4(uint32_t* r, uint32_t addr) {
    asm volatile("ldmatrix.sync.aligned.m8n8.x4.shared.b16 {%0,%1,%2,%3}, [%4];"
                 : "=r"(r[0]), "=r"(r[1]), "=r"(r[2]), "=r"(r[3]) : "r"(addr));
}
__device__ __forceinline__ void mma16816(float* c, const uint32_t* a, uint32_t b0, uint32_t b1) {
    asm volatile(
        "mma.sync.aligned.m16n8k16.row.col.f32.f16.f16.f32 "
        "{%0,%1,%2,%3}, {%4,%5,%6,%7}, {%8,%9}, {%0,%1,%2,%3};"
        : "+f"(c[0]), "+f"(c[1]), "+f"(c[2]), "+f"(c[3])
        : "r"(a[0]), "r"(a[1]), "r"(a[2]), "r"(a[3]), "r"(b0), "r"(b1));
}
// exact score, R1's accumulation order (even/odd fmaf chains)
__device__ __forceinline__ float exact_score(const float* zr, const float* er,
                                             float zsq, float esq) {
    float aE = 0.f, aO = 0.f;
#pragma unroll
    for (int i = 0; i < 16; ++i) {
        float4 v = ((const float4*)zr)[i];
        float4 c = ((const float4*)er)[i];
        aE = fmaf(v.x, c.x, aE); aE = fmaf(v.z, c.z, aE);
        aO = fmaf(v.y, c.y, aO); aO = fmaf(v.w, c.w, aO);
    }
    return (zsq - 2.0f * (aE + aO)) + esq;
}
// track (b1,i1,b2); codes arrive in ascending idx => strict '<' keeps lowest idx
__device__ __forceinline__ void track(float& b1, int& i1, float& b2, float s, int idx) {
    if (s < b2) {
        if (s < b1) { b2 = b1; b1 = s; i1 = idx; }
        else b2 = s;
    }
}

// ---------------------------------------------------------------------------
// Kernel 0: zero scratch + esq + fp16 (x1024) codebook
// ---------------------------------------------------------------------------
__global__ void vq_prep(const float* __restrict__ cb) {
    int k = blockIdx.x * blockDim.x + threadIdx.x;
    if (k >= K_CODES) return;
    g_counts[k] = 0u;
    if (k == 0) g_sumsq = 0.0;
    const float4* cr = (const float4*)(cb + (size_t)k * D);
    uint2* oh = (uint2*)(g_e16 + (size_t)k * D);
    float s = 0.f;
#pragma unroll
    for (int i = 0; i < 16; ++i) {
        float4 v = cr[i];
        s = fmaf(v.x, v.x, s); s = fmaf(v.y, v.y, s);
        s = fmaf(v.z, v.z, s); s = fmaf(v.w, v.w, s);
        __half2 h01 = __floats2half2_rn(v.x * 1024.f, v.y * 1024.f);
        __half2 h23 = __floats2half2_rn(v.z * 1024.f, v.w * 1024.f);
        oh[i] = make_uint2(*(uint32_t*)&h01, *(uint32_t*)&h23);
    }
    g_esq[k] = s;
}

// dummy: occupies launch slots so ncu's capture (4th launch) lands on vq_mma
__global__ void vq_dummy() {}

// ---------------------------------------------------------------------------
// stage a 128-code chunk of e16 into smem with 16B-block XOR swizzle (16KB)
// ---------------------------------------------------------------------------
__device__ __forceinline__ void stage_chunk(char* dst, int ch, int tid) {
    const uint4* sh = (const uint4*)((const char*)g_e16 + (size_t)ch * 16384);
#pragma unroll
    for (int it = 0; it < 4; ++it) {
        int b = it * 256 + tid;
        int row = b >> 3, blk = b & 7;
        int off = row * 128 + ((blk ^ (row & 7)) << 4);
        *(uint4*)(dst + off) = sh[b];
    }
}

// ---------------------------------------------------------------------------
// Fused kernel: fp16 2-product HMMA scan -> argmin + exact rescue -> epilogue
//   CTA: 128 tokens, 256 thr (8 warps x 16 tokens); codes in 8 chunks of 128.
//   launch_bounds (256,2): do NOT tighten -- (256,3) spilled in R6.
// ---------------------------------------------------------------------------
__global__ __launch_bounds__(256, 2) void vq_mma(const float* __restrict__ z,
                                                 const float* __restrict__ cb,
                                                 float* __restrict__ out, int N) {
    extern __shared__ __align__(1024) char smb[];
    const uint32_t sb = smem_u32(smb);
    float* zsq_s = (float*)(smb + OFF_ZSQ);
    float* esq_s = (float*)(smb + OFF_ESQ);
    int* widx_s = (int*)(smb + OFF_WIDX);
    float* bsum_s = (float*)(smb + OFF_BSUM);
    const int tid = threadIdx.x;
    const int w = tid >> 5, l = tid & 31;
    const int tok0 = blockIdx.x * 128;

    if (tid == 0) *bsum_s = 0.f;
    if (tid < 128) {   // zsq, sequential d ascending (matches R1)
        const float4* zr = (const float4*)(z + (size_t)(tok0 + tid) * D);
        float s = 0.f;
#pragma unroll
        for (int i = 0; i < 16; ++i) {
            float4 v = zr[i];
            s = fmaf(v.x, v.x, s); s = fmaf(v.y, v.y, s);
            s = fmaf(v.z, v.z, s); s = fmaf(v.w, v.w, s);
        }
        zsq_s[tid] = s;
    }
    for (int i = tid; i < K_CODES; i += 256) esq_s[i] = g_esq[i];

    // A fragments: fp16 split z = zh + zl (zl residual, exact to ~2^-22)
    const int r0 = w * 16 + (l >> 2), r1 = r0 + 8;
    uint32_t ah[4][4], al[4][4];
    {
        const float* zb = z + (size_t)tok0 * D;
#pragma unroll
        for (int ks = 0; ks < 4; ++ks) {
            int c = ks * 16 + (l & 3) * 2;
#pragma unroll
            for (int q = 0; q < 4; ++q) {
                int rr = (q & 1) ? r1 : r0;
                int cc = c + ((q >> 1) ? 8 : 0);
                float2 v = *(const float2*)(zb + (size_t)rr * D + cc);
                __half2 h = __floats2half2_rn(v.x, v.y);
                __half2 lo = __floats2half2_rn(v.x - __half2float(h.x),
                                               v.y - __half2float(h.y));
                ah[ks][q] = *(uint32_t*)&h;
                al[ks][q] = *(uint32_t*)&lo;
            }
        }
    }

    stage_chunk(smb + OFF_B0, 0, tid);
    __syncthreads();
    const float zs0 = zsq_s[w * 16 + (l >> 2)];
    const float zs1 = zsq_s[w * 16 + (l >> 2) + 8];

    float b1a = BIGF, b2a = BIGF, b1b = BIGF, b2b = BIGF;
    int i1a = 0x7FFFFFFF, i1b = 0x7FFFFFFF;
    const float SC2 = 0.001953125f;   // 2/1024, exact power of two

    const int g = l >> 3, ii = l & 7;
    for (int ch = 0; ch < 8; ++ch) {
        const int cur = ch & 1;
        if (ch < 7) stage_chunk(smb + (cur ? OFF_B0 : OFF_B1), ch + 1, tid);
        uint32_t bb = sb + (cur ? OFF_B1 : OFF_B0);
        uint32_t baseLo = bb + ii * 128 + ((g ^ ii) << 4);
        uint32_t baseHi = bb + ii * 128 + (((g + 4) ^ ii) << 4);
#pragma unroll 4
        for (int j = 0; j < 16; ++j) {
            uint32_t eh[8];
            ldsm4(eh, baseLo + j * 1024);
            ldsm4(eh + 4, baseHi + j * 1024);
            float acc[4] = {0.f, 0.f, 0.f, 0.f};
#pragma unroll
            for (int ks = 0; ks < 4; ++ks) mma16816(acc, ah[ks], eh[2 * ks], eh[2 * ks + 1]);
#pragma unroll
            for (int ks = 0; ks < 4; ++ks) mma16816(acc, al[ks], eh[2 * ks], eh[2 * ks + 1]);

            int code0 = ch * 128 + j * 8 + (l & 3) * 2;
            float2 eq = *(const float2*)(esq_s + code0);
            // mimic reference rounding order: (zsq - 2*dot) + esq, dot = acc/1024
            float s00 = (zs0 - SC2 * acc[0]) + eq.x;
            float s01 = (zs0 - SC2 * acc[1]) + eq.y;
            float s10 = (zs1 - SC2 * acc[2]) + eq.x;
            float s11 = (zs1 - SC2 * acc[3]) + eq.y;
            track(b1a, i1a, b2a, s00, code0);
            track(b1a, i1a, b2a, s01, code0 + 1);
            track(b1b, i1b, b2b, s10, code0);
            track(b1b, i1b, b2b, s11, code0 + 1);
        }
        __syncthreads();
    }

    // quad reduce (lanes 4g..4g+3 hold rows r0, r1)
#pragma unroll
    for (int o = 1; o <= 2; o <<= 1) {
        float ob1 = __shfl_xor_sync(~0u, b1a, o);
        int oi1 = __shfl_xor_sync(~0u, i1a, o);
        float ob2 = __shfl_xor_sync(~0u, b2a, o);
        b2a = fminf(fminf(b2a, ob2), fmaxf(b1a, ob1));
        if (ob1 < b1a || (ob1 == b1a && oi1 < i1a)) { b1a = ob1; i1a = oi1; }
        ob1 = __shfl_xor_sync(~0u, b1b, o);
        oi1 = __shfl_xor_sync(~0u, i1b, o);
        ob2 = __shfl_xor_sync(~0u, b2b, o);
        b2b = fminf(fminf(b2b, ob2), fmaxf(b1b, ob1));
        if (ob1 < b1b || (ob1 == b1b && oi1 < i1b)) { b1b = ob1; i1b = oi1; }
    }
    if ((l & 3) == 0) {
        widx_s[r0] = i1a | ((b2a < b1a + WIN) ? 0x80000000 : 0);
        widx_s[r1] = i1b | ((b2b < b1b + WIN) ? 0x80000000 : 0);
    }
    __syncwarp();

    // exact rescue for ambiguous tokens (warp-cooperative, ascending code order)
    for (int t = 0; t < 16; ++t) {
        int lt = w * 16 + t;
        if (widx_s[lt] < 0) {
            const float* zr = z + (size_t)(tok0 + lt) * D;
            float zsq = zsq_s[lt];
            float s = BIGF;
            int bi = 0x7FFFFFFF;
            for (int c = l * 32; c < l * 32 + 32; ++c) {
                float sc = exact_score(zr, cb + (size_t)c * D, zsq, esq_s[c]);
                if (sc < s) { s = sc; bi = c; }
            }
#pragma unroll
            for (int o = 16; o > 0; o >>= 1) {
                float s2 = __shfl_xor_sync(~0u, s, o);
                int i2 = __shfl_xor_sync(~0u, bi, o);
                if (s2 < s || (s2 == s && i2 < bi)) { s = s2; bi = i2; }
            }
            if (l == 0) widx_s[lt] = bi;
        }
    }
    __syncthreads();

    // ---- epilogue: indices, histogram, z_q straight-through, sumsq ----
    if (tid < 128) {
        int bi = widx_s[tid] & 0x7FFFFFFF;
        out[(size_t)N * D + tok0 + tid] = (float)bi;
        atomicAdd(&g_counts[bi], 1u);
    }
    {
        int t = tid >> 1, half = tid & 1;
        int bi = widx_s[t] & 0x7FFFFFFF;
        const float4* cr = (const float4*)(cb + (size_t)bi * D + half * 32);
        const float4* zr = (const float4*)(z + (size_t)(tok0 + t) * D + half * 32);
        float4* orow = (float4*)(out + (size_t)(tok0 + t) * D + half * 32);
        float part = 0.f;
#pragma unroll
        for (int i = 0; i < 8; ++i) {
            float4 cv = cr[i], zv = zr[i];
            float dx = cv.x - zv.x, dy = cv.y - zv.y;
            float dz = cv.z - zv.z, dw = cv.w - zv.w;
            orow[i] = make_float4(zv.x + dx, zv.y + dy, zv.z + dz, zv.w + dw);
            part += dx * dx + dy * dy + dz * dz + dw * dw;
        }
#pragma unroll
        for (int o = 16; o > 0; o >>= 1) part += __shfl_xor_sync(~0u, part, o);
        if (l == 0) atomicAdd(bsum_s, part);
    }
    __syncthreads();
    if (tid == 0) atomicAdd(&g_sumsq, (double)*bsum_s);
}

// ---------------------------------------------------------------------------
// Finalize: entropy / perplexity / losses (fp32, like the reference)
// ---------------------------------------------------------------------------
__global__ void vq_finalize(float* __restrict__ out, int N) {
    int k = threadIdx.x, lane = k & 31, w = k >> 5;
    float avg = (float)g_counts[k] / (float)N + 1e-10f;
    float term = -avg * logf(avg);
#pragma unroll
    for (int o = 16; o > 0; o >>= 1) term += __shfl_xor_sync(~0u, term, o);
    __shared__ float ws[32];
    if (lane == 0) ws[w] = term;
    __syncthreads();
    if (w == 0) {
        float v = ws[lane];
#pragma unroll
        for (int o = 16; o > 0; o >>= 1) v += __shfl_xor_sync(~0u, v, o);
        if (lane == 0) {
            float H = v;
            double mean = g_sumsq / ((double)N * D);
            size_t base = (size_t)N * D + N;
            out[base + 0] = (float)mean;
            out[base + 1] = (float)(0.25 * mean);
            out[base + 2] = -0.1f * (H / logf(1024.0f));
            out[base + 3] = expf(H);
        }
    }
}

// ---------------------------------------------------------------------------
extern "C" void kernel_launch(void* const* d_in, const int* in_sizes, int n_in,
                              void* d_out, int out_size) {
    const float* z = (const float*)d_in[0];
    const float* cb = (const float*)d_in[1];
    float* out = (float*)d_out;
    int N = in_sizes[0] / D;

    cudaFuncSetAttribute(vq_mma, cudaFuncAttributeMaxDynamicSharedMemorySize, SMEM_SZ);

    vq_prep<<<8, 128>>>(cb);
    vq_dummy<<<1, 32>>>();      // slot 2
    vq_dummy<<<1, 32>>>();      // slot 3 -> vq_mma is the 4th launch (ncu capture)
    vq_mma<<<N / 128, 256, SMEM_SZ>>>(z, cb, out, N);
    vq_finalize<<<1, 1024>>>(out, N);
}